// round 1
// baseline (speedup 1.0000x reference)
#include <cuda_runtime.h>
#include <cuda_bf16.h>
#include <math.h>

#define F 256            // F_IN == F_OUT == 256
#define N_MAX 50048
#define E_MAX 800256

// -------- device scratch (no allocations allowed) --------
__device__ float g_agg[(size_t)N_MAX * F];   // in_deg^-1/2-scaled aggregation
__device__ float g_sin[N_MAX];               // in_deg^-1/2 per row
__device__ int   g_cnt[N_MAX];               // in-degree histogram
__device__ int   g_out[N_MAX];               // out-degree histogram
__device__ int   g_fill[N_MAX];              // CSR fill cursors
__device__ int   g_scan[N_MAX];              // per-block inclusive scan
__device__ int   g_roff[N_MAX + 1];          // CSR row offsets
__device__ int   g_eidx[E_MAX];              // dst-sorted edge ids
__device__ int   g_bsums[64];                // scan block sums

// ---------------------------------------------------------
__global__ void zero_kernel(int n) {
    int i = blockIdx.x * blockDim.x + threadIdx.x;
    if (i < n) { g_cnt[i] = 0; g_out[i] = 0; }
}

__global__ void hist_kernel(const int* __restrict__ src,
                            const int* __restrict__ dst, int e) {
    int i = blockIdx.x * blockDim.x + threadIdx.x;
    if (i < e) {
        atomicAdd(&g_cnt[dst[i]], 1);
        atomicAdd(&g_out[src[i]], 1);
    }
}

// block-level inclusive scan (1024 threads), block sums to g_bsums
__global__ void scan1_kernel(int n) {
    __shared__ int sh[1024];
    int t = threadIdx.x;
    int i = blockIdx.x * 1024 + t;
    int v = (i < n) ? g_cnt[i] : 0;
    sh[t] = v; __syncthreads();
    #pragma unroll
    for (int off = 1; off < 1024; off <<= 1) {
        int x = sh[t];
        if (t >= off) x += sh[t - off];
        __syncthreads();
        sh[t] = x;
        __syncthreads();
    }
    if (i < n) g_scan[i] = sh[t];
    if (t == 1023) g_bsums[blockIdx.x] = sh[t];
}

// exclusive scan of <=64 block sums
__global__ void scan2_kernel(int nb) {
    __shared__ int sh[64];
    int t = threadIdx.x;
    int v = (t < nb) ? g_bsums[t] : 0;
    sh[t] = v; __syncthreads();
    #pragma unroll
    for (int off = 1; off < 64; off <<= 1) {
        int x = sh[t];
        if (t >= off) x += sh[t - off];
        __syncthreads();
        sh[t] = x;
        __syncthreads();
    }
    if (t < nb) g_bsums[t] = sh[t] - v;   // exclusive
}

__global__ void scan3_kernel(int n) {
    int i = blockIdx.x * blockDim.x + threadIdx.x;
    if (i < n) {
        int incl = g_scan[i] + g_bsums[i >> 10];
        g_roff[i + 1] = incl;
        g_fill[i] = incl - g_cnt[i];
        if (i == 0) g_roff[0] = 0;
    }
}

__global__ void fill_kernel(const int* __restrict__ dst, int e) {
    int i = blockIdx.x * blockDim.x + threadIdx.x;
    if (i < e) {
        int p = atomicAdd(&g_fill[dst[i]], 1);
        g_eidx[p] = i;
    }
}

// one warp per dst row: register accumulation, single write, no fp atomics
__global__ void aggregate_kernel(const float* __restrict__ feature,
                                 const float* __restrict__ e_w,
                                 const int* __restrict__ src,
                                 int n) {
    int wid  = (blockIdx.x * blockDim.x + threadIdx.x) >> 5;
    int lane = threadIdx.x & 31;
    if (wid >= n) return;
    int beg = g_roff[wid], end = g_roff[wid + 1];
    float4 a0 = make_float4(0.f, 0.f, 0.f, 0.f);
    float4 a1 = a0;
    for (int k = beg; k < end; ++k) {
        int e = g_eidx[k];
        int s = src[e];
        float sc = e_w[e] * rsqrtf(fmaxf((float)g_out[s], 1.0f));
        const float4* fr = (const float4*)(feature + (size_t)s * F);
        float4 f0 = fr[lane];
        float4 f1 = fr[lane + 32];
        a0.x += f0.x * sc; a0.y += f0.y * sc; a0.z += f0.z * sc; a0.w += f0.w * sc;
        a1.x += f1.x * sc; a1.y += f1.y * sc; a1.z += f1.z * sc; a1.w += f1.w * sc;
    }
    float si = rsqrtf(fmaxf((float)(end - beg), 1.0f));
    a0.x *= si; a0.y *= si; a0.z *= si; a0.w *= si;
    a1.x *= si; a1.y *= si; a1.z *= si; a1.w *= si;
    float4* ar = (float4*)(g_agg + (size_t)wid * F);
    ar[lane]      = a0;
    ar[lane + 32] = a1;
    if (lane == 0) g_sin[wid] = si;
}

// fused: out = feature@W_self + (agg*s_in)@W + s_in*b
// 128x128 block tile, BK=8, 256 threads, 8x8 per thread
__global__ void __launch_bounds__(256, 2)
gemm_kernel(const float* __restrict__ A0,     // feature [n,256]
            const float* __restrict__ B0,     // W_self  [256,256]
            const float* __restrict__ B1,     // W       [256,256]
            const float* __restrict__ bias,   // b [256]
            float* __restrict__ out, int n) {
    __shared__ float As[8][128];
    __shared__ float Bs[8][128];
    int tid = threadIdx.x;
    int tx = tid & 15, ty = tid >> 4;
    int rowBase = blockIdx.x * 128;
    int colBase = blockIdx.y * 128;

    int arow = tid >> 1;            // 0..127
    int acol = (tid & 1) * 4;       // 0 or 4
    int brow = tid >> 5;            // 0..7
    int bcol = (tid & 31) * 4;

    float acc[8][8];
    #pragma unroll
    for (int i = 0; i < 8; ++i)
        #pragma unroll
        for (int j = 0; j < 8; ++j) acc[i][j] = 0.f;

    #pragma unroll 1
    for (int p = 0; p < 2; ++p) {
        const float* A = (p == 0) ? A0 : (const float*)g_agg;
        const float* B = (p == 0) ? B0 : B1;
        #pragma unroll 1
        for (int k0 = 0; k0 < 256; k0 += 8) {
            int gr = rowBase + arow;
            float4 av = make_float4(0.f, 0.f, 0.f, 0.f);
            if (gr < n) av = *(const float4*)(A + (size_t)gr * F + k0 + acol);
            As[acol + 0][arow] = av.x;
            As[acol + 1][arow] = av.y;
            As[acol + 2][arow] = av.z;
            As[acol + 3][arow] = av.w;
            *(float4*)&Bs[brow][bcol] =
                *(const float4*)(B + (size_t)(k0 + brow) * F + colBase + bcol);
            __syncthreads();
            #pragma unroll
            for (int kk = 0; kk < 8; ++kk) {
                float ra[8], rb[8];
                *(float4*)(ra)     = *(const float4*)&As[kk][ty * 8];
                *(float4*)(ra + 4) = *(const float4*)&As[kk][ty * 8 + 4];
                *(float4*)(rb)     = *(const float4*)&Bs[kk][tx * 8];
                *(float4*)(rb + 4) = *(const float4*)&Bs[kk][tx * 8 + 4];
                #pragma unroll
                for (int i = 0; i < 8; ++i)
                    #pragma unroll
                    for (int j = 0; j < 8; ++j)
                        acc[i][j] += ra[i] * rb[j];
            }
            __syncthreads();
        }
    }

    float bb[8];
    #pragma unroll
    for (int j = 0; j < 8; ++j) bb[j] = bias[colBase + tx * 8 + j];
    #pragma unroll
    for (int i = 0; i < 8; ++i) {
        int gr = rowBase + ty * 8 + i;
        if (gr < n) {
            float si = g_sin[gr];
            float4 v0, v1;
            v0.x = acc[i][0] + si * bb[0];
            v0.y = acc[i][1] + si * bb[1];
            v0.z = acc[i][2] + si * bb[2];
            v0.w = acc[i][3] + si * bb[3];
            v1.x = acc[i][4] + si * bb[4];
            v1.y = acc[i][5] + si * bb[5];
            v1.z = acc[i][6] + si * bb[6];
            v1.w = acc[i][7] + si * bb[7];
            float* op = out + (size_t)gr * F + colBase + tx * 8;
            *(float4*)(op)     = v0;
            *(float4*)(op + 4) = v1;
        }
    }
}

extern "C" void kernel_launch(void* const* d_in, const int* in_sizes, int n_in,
                              void* d_out, int out_size) {
    const float* feature = (const float*)d_in[0];   // [N,256]
    const float* e_w     = (const float*)d_in[1];   // [E,1]
    const float* W_self  = (const float*)d_in[4];   // [256,256]
    const float* W       = (const float*)d_in[5];   // [256,256]
    const float* b       = (const float*)d_in[6];   // [256]
    const int*   src     = (const int*)d_in[7];     // [E]
    const int*   dst     = (const int*)d_in[8];     // [E]
    float*       out     = (float*)d_out;

    int n = in_sizes[0] / F;     // 50000
    int e = in_sizes[1];         // 800000

    zero_kernel<<<(n + 255) / 256, 256>>>(n);
    hist_kernel<<<(e + 255) / 256, 256>>>(src, dst, e);
    int nb = (n + 1023) / 1024;
    scan1_kernel<<<nb, 1024>>>(n);
    scan2_kernel<<<1, 64>>>(nb);
    scan3_kernel<<<(n + 255) / 256, 256>>>(n);
    fill_kernel<<<(e + 255) / 256, 256>>>(dst, e);

    {
        long long threads = (long long)n * 32;
        int blocks = (int)((threads + 255) / 256);
        aggregate_kernel<<<blocks, 256>>>(feature, e_w, src, n);
    }

    dim3 grid((n + 127) / 128, F / 128);
    gemm_kernel<<<grid, 256>>>(feature, W_self, W, b, out, n);

    // second reference output: e_w passthrough, appended after h
    if (out_size >= n * F + e) {
        cudaMemcpyAsync(out + (size_t)n * F, e_w, (size_t)e * sizeof(float),
                        cudaMemcpyDeviceToDevice, 0);
    }
}

// round 2
// speedup vs baseline: 1.6832x; 1.6832x over previous
#include <cuda_runtime.h>
#include <cuda_bf16.h>
#include <math.h>
#include <stdint.h>

#define F 256            // F_IN == F_OUT == 256
#define N_MAX 50048
#define E_MAX 800256

// -------- device scratch (no allocations allowed) --------
__device__ float g_agg[(size_t)N_MAX * F];   // in_deg^-1/2-scaled aggregation
__device__ float g_sin[N_MAX];               // in_deg^-1/2 per row
__device__ float g_outr[N_MAX];              // out_deg^-1/2 per row
__device__ int   g_cnt[N_MAX];               // in-degree histogram
__device__ int   g_outd[N_MAX];              // out-degree histogram
__device__ int   g_fill[N_MAX];              // CSR fill cursors
__device__ int   g_scan[N_MAX];              // per-block inclusive scan
__device__ int   g_roff[N_MAX + 1];          // CSR row offsets
__device__ int   g_esrc[E_MAX];              // dst-sorted src ids
__device__ float g_esc[E_MAX];               // dst-sorted edge scale (e_w * outr[src])
__device__ int   g_bsums[64];                // scan block sums

// ---------------------------------------------------------
__global__ void zero_kernel(int n) {
    int i = blockIdx.x * blockDim.x + threadIdx.x;
    if (i < n) { g_cnt[i] = 0; g_outd[i] = 0; }
}

__global__ void hist_kernel(const int* __restrict__ src,
                            const int* __restrict__ dst, int e) {
    int i = blockIdx.x * blockDim.x + threadIdx.x;
    if (i < e) {
        atomicAdd(&g_cnt[dst[i]], 1);
        atomicAdd(&g_outd[src[i]], 1);
    }
}

// block-level inclusive scan (1024 threads), block sums to g_bsums
__global__ void scan1_kernel(int n) {
    __shared__ int sh[1024];
    int t = threadIdx.x;
    int i = blockIdx.x * 1024 + t;
    int v = (i < n) ? g_cnt[i] : 0;
    sh[t] = v; __syncthreads();
    #pragma unroll
    for (int off = 1; off < 1024; off <<= 1) {
        int x = sh[t];
        if (t >= off) x += sh[t - off];
        __syncthreads();
        sh[t] = x;
        __syncthreads();
    }
    if (i < n) g_scan[i] = sh[t];
    if (t == 1023) g_bsums[blockIdx.x] = sh[t];
}

// finish scan: every block redundantly prefixes the <=64 block sums
__global__ void scan23_kernel(int n, int nb) {
    __shared__ int pre[64];
    if (threadIdx.x == 0) {
        int a = 0;
        for (int j = 0; j < nb; ++j) { pre[j] = a; a += g_bsums[j]; }
    }
    __syncthreads();
    int i = blockIdx.x * blockDim.x + threadIdx.x;
    if (i < n) {
        int incl = g_scan[i] + pre[i >> 10];
        g_roff[i + 1] = incl;
        g_fill[i] = incl - g_cnt[i];
        g_outr[i] = rsqrtf(fmaxf((float)g_outd[i], 1.0f));
        if (i == 0) g_roff[0] = 0;
    }
}

__global__ void fill_kernel(const int* __restrict__ src,
                            const int* __restrict__ dst,
                            const float* __restrict__ e_w, int e) {
    int i = blockIdx.x * blockDim.x + threadIdx.x;
    if (i < e) {
        int s = src[i];
        int p = atomicAdd(&g_fill[dst[i]], 1);
        g_esrc[p] = s;
        g_esc[p] = e_w[i] * g_outr[s];
    }
}

// one warp per dst row: register accumulation, single write, no fp atomics
__global__ void __launch_bounds__(512)
aggregate_kernel(const float* __restrict__ feature, int n) {
    int row  = blockIdx.x * 16 + (threadIdx.x >> 5);
    int lane = threadIdx.x & 31;
    if (row >= n) return;
    int beg = g_roff[row], end = g_roff[row + 1];
    float4 a0 = make_float4(0.f, 0.f, 0.f, 0.f);
    float4 a1 = a0;
    for (int base = beg; base < end; base += 32) {
        int m = min(32, end - base);
        int   sE = 0; float cE = 0.f;
        if (lane < m) { sE = g_esrc[base + lane]; cE = g_esc[base + lane]; }
        #pragma unroll 4
        for (int j = 0; j < m; ++j) {
            int   ss = __shfl_sync(0xffffffffu, sE, j);
            float sc = __shfl_sync(0xffffffffu, cE, j);
            const float4* fr = (const float4*)(feature + (size_t)ss * F);
            float4 f0 = fr[lane];
            float4 f1 = fr[lane + 32];
            a0.x += f0.x * sc; a0.y += f0.y * sc; a0.z += f0.z * sc; a0.w += f0.w * sc;
            a1.x += f1.x * sc; a1.y += f1.y * sc; a1.z += f1.z * sc; a1.w += f1.w * sc;
        }
    }
    float si = rsqrtf(fmaxf((float)(end - beg), 1.0f));
    a0.x *= si; a0.y *= si; a0.z *= si; a0.w *= si;
    a1.x *= si; a1.y *= si; a1.z *= si; a1.w *= si;
    float4* ar = (float4*)(g_agg + (size_t)row * F);
    ar[lane]      = a0;
    ar[lane + 32] = a1;
    if (lane == 0) g_sin[row] = si;
}

// ============== bf16 split tensor-core GEMM =================
// out = feature@W_self + g_agg@W + s_in*b, 3-term bf16 split per product.
// Block tile 128x128, BK=32, 8 warps (4m x 2n), warp tile 32x64.

struct SmemGemm {
    __nv_bfloat16 AsH[128][40];
    __nv_bfloat16 AsL[128][40];
    __nv_bfloat16 BsH[32][136];
    __nv_bfloat16 BsL[32][136];
};

__device__ __forceinline__ uint32_t sptr(const void* p) {
    return (uint32_t)__cvta_generic_to_shared(p);
}
__device__ __forceinline__ void ldsm4(unsigned r[4], uint32_t a) {
    asm volatile("ldmatrix.sync.aligned.m8n8.x4.shared.b16 {%0,%1,%2,%3}, [%4];\n"
        : "=r"(r[0]), "=r"(r[1]), "=r"(r[2]), "=r"(r[3]) : "r"(a));
}
__device__ __forceinline__ void ldsm4t(unsigned r[4], uint32_t a) {
    asm volatile("ldmatrix.sync.aligned.m8n8.x4.trans.shared.b16 {%0,%1,%2,%3}, [%4];\n"
        : "=r"(r[0]), "=r"(r[1]), "=r"(r[2]), "=r"(r[3]) : "r"(a));
}
__device__ __forceinline__ void mma_bf16(float* d, const unsigned a[4],
                                         unsigned b0, unsigned b1) {
    asm volatile(
        "mma.sync.aligned.m16n8k16.row.col.f32.bf16.bf16.f32 "
        "{%0,%1,%2,%3}, {%4,%5,%6,%7}, {%8,%9}, {%0,%1,%2,%3};\n"
        : "+f"(d[0]), "+f"(d[1]), "+f"(d[2]), "+f"(d[3])
        : "r"(a[0]), "r"(a[1]), "r"(a[2]), "r"(a[3]), "r"(b0), "r"(b1));
}
__device__ __forceinline__ unsigned pk(__nv_bfloat16 a, __nv_bfloat16 b) {
    __nv_bfloat162 t = __halves2bfloat162(a, b);
    return *(unsigned*)&t;
}
__device__ __forceinline__ void cvt_hl(float x, __nv_bfloat16& h, __nv_bfloat16& l) {
    h = __float2bfloat16(x);
    l = __float2bfloat16(x - __bfloat162float(h));
}

__global__ void __launch_bounds__(256)
gemm_kernel(const float* __restrict__ feature,  // [n,256]
            const float* __restrict__ W_self,   // [256,256]
            const float* __restrict__ W,        // [256,256]
            const float* __restrict__ bias,     // [256]
            float* __restrict__ out, int n) {
    __shared__ SmemGemm s;
    const float* Aagg = (const float*)g_agg;

    int tid  = threadIdx.x;
    int wid  = tid >> 5, lane = tid & 31;
    int wm   = wid & 3, wn = wid >> 2;           // 4 x 2 warp grid
    int mBase = (blockIdx.x >> 1) * 128;
    int nBase = (blockIdx.x & 1) * 128;

    int arow = tid >> 1, acb = (tid & 1) * 16;   // A: 128 rows x 32 k
    int brow = tid >> 3, bcb = (tid & 7) * 16;   // B: 32 rows  x 128 n

    float acc[2][8][4];
    #pragma unroll
    for (int i = 0; i < 2; ++i)
        #pragma unroll
        for (int j = 0; j < 8; ++j)
            #pragma unroll
            for (int q = 0; q < 4; ++q) acc[i][j][q] = 0.f;

    float4 rA[4], rB[4];
    int grow = mBase + arow;

    // prefetch iter 0 (pass 0, k0 = 0)
    #pragma unroll
    for (int j = 0; j < 4; ++j) {
        int col = acb + j * 4;
        rA[j] = make_float4(0.f, 0.f, 0.f, 0.f);
        if (grow < n) rA[j] = *(const float4*)(feature + (size_t)grow * F + col);
        rB[j] = *(const float4*)(W_self + (size_t)brow * F + nBase + bcb + j * 4);
    }

    #pragma unroll 1
    for (int it = 0; it < 16; ++it) {
        // store prefetched registers into smem (hi/lo split)
        #pragma unroll
        for (int j = 0; j < 4; ++j) {
            int colA = acb + j * 4;
            __nv_bfloat16 h0, h1, h2, h3, l0, l1, l2, l3;
            cvt_hl(rA[j].x, h0, l0); cvt_hl(rA[j].y, h1, l1);
            cvt_hl(rA[j].z, h2, l2); cvt_hl(rA[j].w, h3, l3);
            *(uint2*)&s.AsH[arow][colA] = make_uint2(pk(h0, h1), pk(h2, h3));
            *(uint2*)&s.AsL[arow][colA] = make_uint2(pk(l0, l1), pk(l2, l3));
            int colB = bcb + j * 4;
            cvt_hl(rB[j].x, h0, l0); cvt_hl(rB[j].y, h1, l1);
            cvt_hl(rB[j].z, h2, l2); cvt_hl(rB[j].w, h3, l3);
            *(uint2*)&s.BsH[brow][colB] = make_uint2(pk(h0, h1), pk(h2, h3));
            *(uint2*)&s.BsL[brow][colB] = make_uint2(pk(l0, l1), pk(l2, l3));
        }
        __syncthreads();

        // prefetch next iter
        if (it + 1 < 16) {
            int p2 = (it + 1) >> 3;
            int k2 = ((it + 1) & 7) * 32;
            const float* A2 = p2 ? Aagg : feature;
            const float* B2 = p2 ? W : W_self;
            #pragma unroll
            for (int j = 0; j < 4; ++j) {
                int col = acb + j * 4;
                rA[j] = make_float4(0.f, 0.f, 0.f, 0.f);
                if (grow < n) rA[j] = *(const float4*)(A2 + (size_t)grow * F + k2 + col);
                rB[j] = *(const float4*)(B2 + (size_t)(k2 + brow) * F + nBase + bcb + j * 4);
            }
        }

        // compute: 2 ksteps of 16
        #pragma unroll
        for (int kt = 0; kt < 2; ++kt) {
            int ks = kt * 16;
            unsigned aH[2][4], aL[2][4];
            #pragma unroll
            for (int mt = 0; mt < 2; ++mt) {
                int r = wm * 32 + mt * 16 + (lane & 15);
                int c = ks + (lane >> 4) * 8;
                ldsm4(aH[mt], sptr(&s.AsH[r][c]));
                ldsm4(aL[mt], sptr(&s.AsL[r][c]));
            }
            #pragma unroll
            for (int nc = 0; nc < 4; ++nc) {
                int rB2 = ks + (lane & 15);
                int cB2 = wn * 64 + nc * 16 + (lane >> 4) * 8;
                unsigned bH[4], bL[4];
                ldsm4t(bH, sptr(&s.BsH[rB2][cB2]));
                ldsm4t(bL, sptr(&s.BsL[rB2][cB2]));
                #pragma unroll
                for (int mt = 0; mt < 2; ++mt) {
                    mma_bf16(acc[mt][nc * 2],     aH[mt], bH[0], bH[1]);
                    mma_bf16(acc[mt][nc * 2],     aL[mt], bH[0], bH[1]);
                    mma_bf16(acc[mt][nc * 2],     aH[mt], bL[0], bL[1]);
                    mma_bf16(acc[mt][nc * 2 + 1], aH[mt], bH[2], bH[3]);
                    mma_bf16(acc[mt][nc * 2 + 1], aL[mt], bH[2], bH[3]);
                    mma_bf16(acc[mt][nc * 2 + 1], aH[mt], bL[2], bL[3]);
                }
            }
        }
        __syncthreads();
    }

    // epilogue: out = acc + s_in * bias
    #pragma unroll
    for (int mt = 0; mt < 2; ++mt) {
        int r0 = mBase + wm * 32 + mt * 16 + (lane >> 2);
        int r1 = r0 + 8;
        float si0 = (r0 < n) ? g_sin[r0] : 0.f;
        float si1 = (r1 < n) ? g_sin[r1] : 0.f;
        #pragma unroll
        for (int nt = 0; nt < 8; ++nt) {
            int c = nBase + wn * 64 + nt * 8 + (lane & 3) * 2;
            float b0 = bias[c], b1 = bias[c + 1];
            float* d = acc[mt][nt];
            if (r0 < n)
                *(float2*)(out + (size_t)r0 * F + c) =
                    make_float2(d[0] + si0 * b0, d[1] + si0 * b1);
            if (r1 < n)
                *(float2*)(out + (size_t)r1 * F + c) =
                    make_float2(d[2] + si1 * b0, d[3] + si1 * b1);
        }
    }
}

extern "C" void kernel_launch(void* const* d_in, const int* in_sizes, int n_in,
                              void* d_out, int out_size) {
    const float* feature = (const float*)d_in[0];   // [N,256]
    const float* e_w     = (const float*)d_in[1];   // [E,1]
    const float* W_self  = (const float*)d_in[4];   // [256,256]
    const float* W       = (const float*)d_in[5];   // [256,256]
    const float* b       = (const float*)d_in[6];   // [256]
    const int*   src     = (const int*)d_in[7];     // [E]
    const int*   dst     = (const int*)d_in[8];     // [E]
    float*       out     = (float*)d_out;

    int n = in_sizes[0] / F;     // 50000
    int e = in_sizes[1];         // 800000

    zero_kernel<<<(n + 255) / 256, 256>>>(n);
    hist_kernel<<<(e + 255) / 256, 256>>>(src, dst, e);
    int nb = (n + 1023) / 1024;
    scan1_kernel<<<nb, 1024>>>(n);
    scan23_kernel<<<(n + 255) / 256, 256>>>(n, nb);
    fill_kernel<<<(e + 255) / 256, 256>>>(src, dst, e_w, e);

    aggregate_kernel<<<(n + 15) / 16, 512>>>(feature, n);

    int rb = (n + 127) / 128;
    gemm_kernel<<<rb * 2, 256>>>(feature, W_self, W, b, out, n);

    // second reference output: e_w passthrough, appended after h
    if (out_size >= n * F + e) {
        cudaMemcpyAsync(out + (size_t)n * F, e_w, (size_t)e * sizeof(float),
                        cudaMemcpyDeviceToDevice, 0);
    }
}

// round 4
// speedup vs baseline: 2.0342x; 1.2085x over previous
#include <cuda_runtime.h>
#include <cuda_bf16.h>
#include <cuda_fp16.h>
#include <math.h>
#include <stdint.h>

#define F 256
#define N_MAX 50048
#define E_MAX 800256

// -------- device scratch --------
__device__ float g_sin[N_MAX];
__device__ float g_outr[N_MAX];
__device__ int   g_cnt[N_MAX];
__device__ int   g_outd[N_MAX];
__device__ int   g_fill[N_MAX];
__device__ int   g_scan[N_MAX];
__device__ int   g_roff[N_MAX + 1];
__device__ int   g_esrc[E_MAX];
__device__ float g_esc[E_MAX];
__device__ int   g_bsums[64];

__device__ __nv_bfloat16 g_featH[(size_t)N_MAX * F];
__device__ __nv_bfloat16 g_featL[(size_t)N_MAX * F];
__device__ __half        g_feat16[(size_t)N_MAX * F];
__device__ __nv_bfloat16 g_aggH[(size_t)N_MAX * F];
__device__ __nv_bfloat16 g_aggL[(size_t)N_MAX * F];
__device__ __nv_bfloat16 g_wsH[F * F], g_wsL[F * F];   // W_self [k][n] bf16
__device__ __nv_bfloat16 g_wH[F * F],  g_wL[F * F];    // W      [k][n] bf16

// -------- helpers --------
__device__ __forceinline__ unsigned pk(__nv_bfloat16 a, __nv_bfloat16 b) {
    __nv_bfloat162 t = __halves2bfloat162(a, b);
    return *(unsigned*)&t;
}
__device__ __forceinline__ void cvt_hl(float x, __nv_bfloat16& h, __nv_bfloat16& l) {
    h = __float2bfloat16(x);
    l = __float2bfloat16(x - __bfloat162float(h));
}
__device__ __forceinline__ uint32_t sptr(const void* p) {
    return (uint32_t)__cvta_generic_to_shared(p);
}
__device__ __forceinline__ void ldsm4(unsigned r[4], uint32_t a) {
    asm volatile("ldmatrix.sync.aligned.m8n8.x4.shared.b16 {%0,%1,%2,%3}, [%4];\n"
        : "=r"(r[0]), "=r"(r[1]), "=r"(r[2]), "=r"(r[3]) : "r"(a));
}
__device__ __forceinline__ void ldsm4t(unsigned r[4], uint32_t a) {
    asm volatile("ldmatrix.sync.aligned.m8n8.x4.trans.shared.b16 {%0,%1,%2,%3}, [%4];\n"
        : "=r"(r[0]), "=r"(r[1]), "=r"(r[2]), "=r"(r[3]) : "r"(a));
}
__device__ __forceinline__ void mma_bf16(float* d, const unsigned a[4],
                                         unsigned b0, unsigned b1) {
    asm volatile(
        "mma.sync.aligned.m16n8k16.row.col.f32.bf16.bf16.f32 "
        "{%0,%1,%2,%3}, {%4,%5,%6,%7}, {%8,%9}, {%0,%1,%2,%3};\n"
        : "+f"(d[0]), "+f"(d[1]), "+f"(d[2]), "+f"(d[3])
        : "r"(a[0]), "r"(a[1]), "r"(a[2]), "r"(a[3]), "r"(b0), "r"(b1));
}
__device__ __forceinline__ void cp16(uint32_t dst, const void* src) {
    asm volatile("cp.async.cg.shared.global [%0], [%1], 16;\n" :: "r"(dst), "l"(src));
}
__device__ __forceinline__ void cp16z(uint32_t dst, const void* src, int sz) {
    asm volatile("cp.async.cg.shared.global [%0], [%1], 16, %2;\n"
                 :: "r"(dst), "l"(src), "r"(sz));
}
__device__ __forceinline__ void cp_commit() {
    asm volatile("cp.async.commit_group;\n" ::: "memory");
}
__device__ __forceinline__ void cp_wait1() {
    asm volatile("cp.async.wait_group 1;\n" ::: "memory");
}
__device__ __forceinline__ void cp_wait0() {
    asm volatile("cp.async.wait_group 0;\n" ::: "memory");
}

// ---------------- CSR build ----------------
__global__ void zero_kernel(int n) {
    int i = blockIdx.x * blockDim.x + threadIdx.x;
    if (i < n) { g_cnt[i] = 0; g_outd[i] = 0; }
}
__global__ void hist_kernel(const int* __restrict__ src,
                            const int* __restrict__ dst, int e) {
    int i = blockIdx.x * blockDim.x + threadIdx.x;
    if (i < e) {
        atomicAdd(&g_cnt[dst[i]], 1);
        atomicAdd(&g_outd[src[i]], 1);
    }
}
__global__ void scan1_kernel(int n) {
    __shared__ int sh[1024];
    int t = threadIdx.x;
    int i = blockIdx.x * 1024 + t;
    int v = (i < n) ? g_cnt[i] : 0;
    sh[t] = v; __syncthreads();
    #pragma unroll
    for (int off = 1; off < 1024; off <<= 1) {
        int x = sh[t];
        if (t >= off) x += sh[t - off];
        __syncthreads();
        sh[t] = x;
        __syncthreads();
    }
    if (i < n) g_scan[i] = sh[t];
    if (t == 1023) g_bsums[blockIdx.x] = sh[t];
}
__global__ void scan23_kernel(int n, int nb) {
    __shared__ int pre[64];
    if (threadIdx.x == 0) {
        int a = 0;
        for (int j = 0; j < nb; ++j) { pre[j] = a; a += g_bsums[j]; }
    }
    __syncthreads();
    int i = blockIdx.x * blockDim.x + threadIdx.x;
    if (i < n) {
        int incl = g_scan[i] + pre[i >> 10];
        g_roff[i + 1] = incl;
        g_fill[i] = incl - g_cnt[i];
        g_outr[i] = rsqrtf(fmaxf((float)g_outd[i], 1.0f));
        if (i == 0) g_roff[0] = 0;
    }
}
__global__ void fill_kernel(const int* __restrict__ src,
                            const int* __restrict__ dst,
                            const float* __restrict__ e_w, int e) {
    int i = blockIdx.x * blockDim.x + threadIdx.x;
    if (i < e) {
        int s = src[i];
        int p = atomicAdd(&g_fill[dst[i]], 1);
        g_esrc[p] = s;
        g_esc[p] = e_w[i] * g_outr[s];
    }
}

// ---------------- conversions ----------------
__global__ void convert_feat_kernel(const float* __restrict__ f, int q) {
    int i = blockIdx.x * blockDim.x + threadIdx.x;
    if (i >= q) return;
    float4 v = ((const float4*)f)[i];
    __nv_bfloat16 h0, h1, h2, h3, l0, l1, l2, l3;
    cvt_hl(v.x, h0, l0); cvt_hl(v.y, h1, l1);
    cvt_hl(v.z, h2, l2); cvt_hl(v.w, h3, l3);
    ((uint2*)g_featH)[i] = make_uint2(pk(h0, h1), pk(h2, h3));
    ((uint2*)g_featL)[i] = make_uint2(pk(l0, l1), pk(l2, l3));
    __half2 p0 = __floats2half2_rn(v.x, v.y);
    __half2 p1 = __floats2half2_rn(v.z, v.w);
    ((uint2*)g_feat16)[i] = make_uint2(*(unsigned*)&p0, *(unsigned*)&p1);
}
__global__ void convert_w_kernel(const float* __restrict__ Ws,
                                 const float* __restrict__ Wn) {
    int i = blockIdx.x * blockDim.x + threadIdx.x;
    if (i >= F * F) return;
    __nv_bfloat16 h, l;
    cvt_hl(Ws[i], h, l);
    g_wsH[i] = h; g_wsL[i] = l;
    cvt_hl(Wn[i], h, l);
    g_wH[i] = h; g_wL[i] = l;
}

// ---------------- aggregation (fp16 gather, bf16 hi/lo out) ----------------
__global__ void __launch_bounds__(512)
aggregate_kernel(int n) {
    int row  = blockIdx.x * 16 + (threadIdx.x >> 5);
    int lane = threadIdx.x & 31;
    if (row >= n) return;
    int beg = g_roff[row], end = g_roff[row + 1];
    float a[8];
    #pragma unroll
    for (int j = 0; j < 8; ++j) a[j] = 0.f;
    for (int base = beg; base < end; base += 32) {
        int m = min(32, end - base);
        int sE = 0; float cE = 0.f;
        if (lane < m) { sE = g_esrc[base + lane]; cE = g_esc[base + lane]; }
        #pragma unroll 4
        for (int j = 0; j < m; ++j) {
            int   ss = __shfl_sync(0xffffffffu, sE, j);
            float sc = __shfl_sync(0xffffffffu, cE, j);
            uint4 d = *(const uint4*)(g_feat16 + (size_t)ss * F + lane * 8);
            float2 f0 = __half22float2(*(__half2*)&d.x);
            float2 f1 = __half22float2(*(__half2*)&d.y);
            float2 f2 = __half22float2(*(__half2*)&d.z);
            float2 f3 = __half22float2(*(__half2*)&d.w);
            a[0] += f0.x * sc; a[1] += f0.y * sc;
            a[2] += f1.x * sc; a[3] += f1.y * sc;
            a[4] += f2.x * sc; a[5] += f2.y * sc;
            a[6] += f3.x * sc; a[7] += f3.y * sc;
        }
    }
    float si = rsqrtf(fmaxf((float)(end - beg), 1.0f));
    __nv_bfloat16 h[8], l[8];
    #pragma unroll
    for (int j = 0; j < 8; ++j) cvt_hl(a[j] * si, h[j], l[j]);
    uint4 H = make_uint4(pk(h[0], h[1]), pk(h[2], h[3]), pk(h[4], h[5]), pk(h[6], h[7]));
    uint4 L = make_uint4(pk(l[0], l[1]), pk(l[2], l[3]), pk(l[4], l[5]), pk(l[6], l[7]));
    *(uint4*)(g_aggH + (size_t)row * F + lane * 8) = H;
    *(uint4*)(g_aggL + (size_t)row * F + lane * 8) = L;
    if (lane == 0) g_sin[row] = si;
}

// ---------------- bf16 3-term split GEMM (mma.sync, double-buffered) ----------
// out = feature@W_self + agg@W + s_in*b
// Block 128x128, BK=32, 8 warps (4m x 2n), warp tile 32x64, 16 iters.
// smem per stage (elements): AH 128x40, AL 128x40, BH 32x136, BL 32x136
#define A_STRIDE 40
#define B_STRIDE 136
#define ST_ELEMS 18944           // 128*40*2 + 32*136*2
#define AH_OFF(s) ((s) * ST_ELEMS)
#define AL_OFF(s) ((s) * ST_ELEMS + 5120)
#define BH_OFF(s) ((s) * ST_ELEMS + 10240)
#define BL_OFF(s) ((s) * ST_ELEMS + 14592)
#define SMEM_DYN (2 * ST_ELEMS * 2)

__device__ __forceinline__ void load_stage(uint32_t sb, __nv_bfloat16* base,
                                           int stage, int it, int mBase, int nBase,
                                           int n, int tid) {
    int p = it >> 3, kc = it & 7, k0 = kc * 32;
    const __nv_bfloat16* AH = p ? g_aggH : g_featH;
    const __nv_bfloat16* AL = p ? g_aggL : g_featL;
    const __nv_bfloat16* BH = p ? g_wH : g_wsH;
    const __nv_bfloat16* BL = p ? g_wL : g_wsL;
    // A: 128 rows x 4 units(16B) each, 512 tasks, 2 per thread
    #pragma unroll
    for (int u = 0; u < 2; ++u) {
        int idx = u * 256 + tid;
        int row = idx >> 2, un = idx & 3;
        int gr = mBase + row;
        int grc = min(gr, n - 1);
        size_t go = (size_t)grc * F + k0 + un * 8;
        int sz = (gr < n) ? 16 : 0;
        uint32_t doff = (uint32_t)(row * A_STRIDE + un * 8) * 2;
        cp16z(sb + (uint32_t)AH_OFF(stage) * 2 + doff, AH + go, sz);
        cp16z(sb + (uint32_t)AL_OFF(stage) * 2 + doff, AL + go, sz);
    }
    // B: 32 rows x 16 units, 512 tasks, 2 per thread
    #pragma unroll
    for (int u = 0; u < 2; ++u) {
        int idx = u * 256 + tid;
        int row = idx >> 4, un = idx & 15;
        size_t go = (size_t)(k0 + row) * F + nBase + un * 8;
        uint32_t doff = (uint32_t)(row * B_STRIDE + un * 8) * 2;
        cp16(sb + (uint32_t)BH_OFF(stage) * 2 + doff, BH + go);
        cp16(sb + (uint32_t)BL_OFF(stage) * 2 + doff, BL + go);
    }
}

__global__ void __launch_bounds__(256, 2)
gemm_kernel(const float* __restrict__ bias, float* __restrict__ out, int n) {
    extern __shared__ __align__(128) char smraw[];
    __nv_bfloat16* base = (__nv_bfloat16*)smraw;
    uint32_t sb = sptr(smraw);

    int tid = threadIdx.x;
    int wid = tid >> 5, lane = tid & 31;
    int wm = wid & 3, wn = wid >> 2;
    int mBase = (blockIdx.x >> 1) * 128;
    int nBase = (blockIdx.x & 1) * 128;

    float acc[2][8][4];
    #pragma unroll
    for (int i = 0; i < 2; ++i)
        #pragma unroll
        for (int j = 0; j < 8; ++j)
            #pragma unroll
            for (int q = 0; q < 4; ++q) acc[i][j][q] = 0.f;

    load_stage(sb, base, 0, 0, mBase, nBase, n, tid); cp_commit();
    load_stage(sb, base, 1, 1, mBase, nBase, n, tid); cp_commit();

    #pragma unroll 1
    for (int it = 0; it < 16; ++it) {
        if (it < 15) cp_wait1(); else cp_wait0();
        __syncthreads();
        int st = it & 1;
        #pragma unroll
        for (int kt = 0; kt < 2; ++kt) {
            int ks = kt * 16;
            unsigned aH[2][4], aL[2][4];
            #pragma unroll
            for (int mt = 0; mt < 2; ++mt) {
                int r = wm * 32 + mt * 16 + (lane & 15);
                int c = ks + (lane >> 4) * 8;
                ldsm4(aH[mt], sptr(base + AH_OFF(st) + r * A_STRIDE + c));
                ldsm4(aL[mt], sptr(base + AL_OFF(st) + r * A_STRIDE + c));
            }
            #pragma unroll
            for (int nc = 0; nc < 4; ++nc) {
                int rB = ks + (lane & 15);
                int cB = wn * 64 + nc * 16 + (lane >> 4) * 8;
                unsigned bH[4], bL[4];
                ldsm4t(bH, sptr(base + BH_OFF(st) + rB * B_STRIDE + cB));
                ldsm4t(bL, sptr(base + BL_OFF(st) + rB * B_STRIDE + cB));
                #pragma unroll
                for (int mt = 0; mt < 2; ++mt) {
                    mma_bf16(acc[mt][nc * 2],     aH[mt], bH[0], bH[1]);
                    mma_bf16(acc[mt][nc * 2],     aL[mt], bH[0], bH[1]);
                    mma_bf16(acc[mt][nc * 2],     aH[mt], bL[0], bL[1]);
                    mma_bf16(acc[mt][nc * 2 + 1], aH[mt], bH[2], bH[3]);
                    mma_bf16(acc[mt][nc * 2 + 1], aL[mt], bH[2], bH[3]);
                    mma_bf16(acc[mt][nc * 2 + 1], aH[mt], bL[2], bL[3]);
                }
            }
        }
        __syncthreads();
        if (it + 2 < 16) {
            load_stage(sb, base, st, it + 2, mBase, nBase, n, tid);
            cp_commit();
        }
    }

    // epilogue: out = acc + s_in * bias
    #pragma unroll
    for (int mt = 0; mt < 2; ++mt) {
        int r0 = mBase + wm * 32 + mt * 16 + (lane >> 2);
        int r1 = r0 + 8;
        float si0 = (r0 < n) ? g_sin[r0] : 0.f;
        float si1 = (r1 < n) ? g_sin[r1] : 0.f;
        #pragma unroll
        for (int nt = 0; nt < 8; ++nt) {
            int c = nBase + wn * 64 + nt * 8 + (lane & 3) * 2;
            float b0 = bias[c], b1 = bias[c + 1];
            float* d = acc[mt][nt];
            if (r0 < n)
                *(float2*)(out + (size_t)r0 * F + c) =
                    make_float2(d[0] + si0 * b0, d[1] + si0 * b1);
            if (r1 < n)
                *(float2*)(out + (size_t)r1 * F + c) =
                    make_float2(d[2] + si1 * b0, d[3] + si1 * b1);
        }
    }
}

extern "C" void kernel_launch(void* const* d_in, const int* in_sizes, int n_in,
                              void* d_out, int out_size) {
    const float* feature = (const float*)d_in[0];
    const float* e_w     = (const float*)d_in[1];
    const float* W_self  = (const float*)d_in[4];
    const float* W       = (const float*)d_in[5];
    const float* b       = (const float*)d_in[6];
    const int*   src     = (const int*)d_in[7];
    const int*   dst     = (const int*)d_in[8];
    float*       out     = (float*)d_out;

    int n = in_sizes[0] / F;
    int e = in_sizes[1];

    static int smem_set = 0;
    if (!smem_set) {
        cudaFuncSetAttribute(gemm_kernel,
                             cudaFuncAttributeMaxDynamicSharedMemorySize, SMEM_DYN);
        smem_set = 1;
    }

    zero_kernel<<<(n + 255) / 256, 256>>>(n);
    hist_kernel<<<(e + 255) / 256, 256>>>(src, dst, e);
    int nb = (n + 1023) / 1024;
    scan1_kernel<<<nb, 1024>>>(n);
    scan23_kernel<<<(n + 255) / 256, 256>>>(n, nb);
    fill_kernel<<<(e + 255) / 256, 256>>>(src, dst, e_w, e);

    int q = n * (F / 4);
    convert_feat_kernel<<<(q + 255) / 256, 256>>>(feature, q);
    convert_w_kernel<<<(F * F + 255) / 256, 256>>>(W_self, W);

    aggregate_kernel<<<(n + 15) / 16, 512>>>(n);

    int rb = (n + 127) / 128;
    gemm_kernel<<<rb * 2, 256, SMEM_DYN>>>(b, out, n);

    if (out_size >= n * F + e) {
        cudaMemcpyAsync(out + (size_t)n * F, e_w, (size_t)e * sizeof(float),
                        cudaMemcpyDeviceToDevice, 0);
    }
}

// round 5
// speedup vs baseline: 2.2587x; 1.1104x over previous
#include <cuda_runtime.h>
#include <cuda_bf16.h>
#include <cuda_fp16.h>
#include <math.h>
#include <stdint.h>

#define F 256
#define N_MAX 50048
#define E_MAX 800256

// -------- device scratch --------
__device__ float g_sin[N_MAX];
__device__ float g_outr[N_MAX];
__device__ int   g_cnt[N_MAX];
__device__ int   g_outd[N_MAX];
__device__ int   g_fill[N_MAX];
__device__ int   g_scan[N_MAX];
__device__ int   g_roff[N_MAX + 1];
__device__ int   g_esrc[E_MAX];
__device__ float g_esc[E_MAX];
__device__ int   g_bsums[64];

__device__ __nv_bfloat16 g_featH[(size_t)N_MAX * F];
__device__ __nv_bfloat16 g_featL[(size_t)N_MAX * F];
__device__ __half        g_feat16[(size_t)N_MAX * F];
__device__ __nv_bfloat16 g_aggH[(size_t)N_MAX * F];
__device__ __nv_bfloat16 g_aggL[(size_t)N_MAX * F];
__device__ __nv_bfloat16 g_wsH[F * F], g_wsL[F * F];   // W_self [k][n]
__device__ __nv_bfloat16 g_wH[F * F],  g_wL[F * F];    // W      [k][n]

// -------- helpers --------
__device__ __forceinline__ unsigned pk(__nv_bfloat16 a, __nv_bfloat16 b) {
    __nv_bfloat162 t = __halves2bfloat162(a, b);
    return *(unsigned*)&t;
}
__device__ __forceinline__ void cvt_hl(float x, __nv_bfloat16& h, __nv_bfloat16& l) {
    h = __float2bfloat16(x);
    l = __float2bfloat16(x - __bfloat162float(h));
}
__device__ __forceinline__ uint32_t sptr(const void* p) {
    return (uint32_t)__cvta_generic_to_shared(p);
}
__device__ __forceinline__ void ldsm4(unsigned r[4], uint32_t a) {
    asm volatile("ldmatrix.sync.aligned.m8n8.x4.shared.b16 {%0,%1,%2,%3}, [%4];\n"
        : "=r"(r[0]), "=r"(r[1]), "=r"(r[2]), "=r"(r[3]) : "r"(a));
}
__device__ __forceinline__ void ldsm4t(unsigned r[4], uint32_t a) {
    asm volatile("ldmatrix.sync.aligned.m8n8.x4.trans.shared.b16 {%0,%1,%2,%3}, [%4];\n"
        : "=r"(r[0]), "=r"(r[1]), "=r"(r[2]), "=r"(r[3]) : "r"(a));
}
__device__ __forceinline__ void mma_bf16(float* d, const unsigned a[4],
                                         unsigned b0, unsigned b1) {
    asm volatile(
        "mma.sync.aligned.m16n8k16.row.col.f32.bf16.bf16.f32 "
        "{%0,%1,%2,%3}, {%4,%5,%6,%7}, {%8,%9}, {%0,%1,%2,%3};\n"
        : "+f"(d[0]), "+f"(d[1]), "+f"(d[2]), "+f"(d[3])
        : "r"(a[0]), "r"(a[1]), "r"(a[2]), "r"(a[3]), "r"(b0), "r"(b1));
}
__device__ __forceinline__ void cp16(uint32_t dst, const void* src) {
    asm volatile("cp.async.cg.shared.global [%0], [%1], 16;\n" :: "r"(dst), "l"(src));
}
__device__ __forceinline__ void cp16z(uint32_t dst, const void* src, int sz) {
    asm volatile("cp.async.cg.shared.global [%0], [%1], 16, %2;\n"
                 :: "r"(dst), "l"(src), "r"(sz));
}
__device__ __forceinline__ void cp_commit() {
    asm volatile("cp.async.commit_group;\n" ::: "memory");
}
__device__ __forceinline__ void cp_wait1() {
    asm volatile("cp.async.wait_group 1;\n" ::: "memory");
}
__device__ __forceinline__ void cp_wait0() {
    asm volatile("cp.async.wait_group 0;\n" ::: "memory");
}

// ---------------- zero ----------------
__global__ void zero_kernel(int n) {
    int i = blockIdx.x * blockDim.x + threadIdx.x;
    if (i < n) { g_cnt[i] = 0; g_outd[i] = 0; }
}

// -------- shared convert work item --------
__device__ __forceinline__ void convert_feat_one(const float* __restrict__ f, int i) {
    float4 v = ((const float4*)f)[i];
    __nv_bfloat16 h0, h1, h2, h3, l0, l1, l2, l3;
    cvt_hl(v.x, h0, l0); cvt_hl(v.y, h1, l1);
    cvt_hl(v.z, h2, l2); cvt_hl(v.w, h3, l3);
    ((uint2*)g_featH)[i] = make_uint2(pk(h0, h1), pk(h2, h3));
    ((uint2*)g_featL)[i] = make_uint2(pk(l0, l1), pk(l2, l3));
    __half2 p0 = __floats2half2_rn(v.x, v.y);
    __half2 p1 = __floats2half2_rn(v.z, v.w);
    ((uint2*)g_feat16)[i] = make_uint2(*(unsigned*)&p0, *(unsigned*)&p1);
}

// ---------------- phase2: hist | convert_feat(lo half) | convert_w --------
__global__ void phase2_kernel(const int* __restrict__ src,
                              const int* __restrict__ dst,
                              const float* __restrict__ feat,
                              const float* __restrict__ Ws,
                              const float* __restrict__ Wn,
                              int e, int qh, int HB, int CB) {
    int b = blockIdx.x, t = threadIdx.x;
    if (b < HB) {
        int i = b * 256 + t;
        if (i < e) {
            atomicAdd(&g_cnt[dst[i]], 1);
            atomicAdd(&g_outd[src[i]], 1);
        }
    } else if (b < HB + CB) {
        int i = (b - HB) * 256 + t;
        if (i < qh) convert_feat_one(feat, i);
    } else {
        int i = (b - HB - CB) * 256 + t;
        if (i < F * F) {
            __nv_bfloat16 h, l;
            cvt_hl(Ws[i], h, l);
            g_wsH[i] = h; g_wsL[i] = l;
            cvt_hl(Wn[i], h, l);
            g_wH[i] = h; g_wL[i] = l;
        }
    }
}

// ---------------- scans ----------------
__global__ void scan1_kernel(int n) {
    __shared__ int sh[1024];
    int t = threadIdx.x;
    int i = blockIdx.x * 1024 + t;
    int v = (i < n) ? g_cnt[i] : 0;
    sh[t] = v; __syncthreads();
    #pragma unroll
    for (int off = 1; off < 1024; off <<= 1) {
        int x = sh[t];
        if (t >= off) x += sh[t - off];
        __syncthreads();
        sh[t] = x;
        __syncthreads();
    }
    if (i < n) g_scan[i] = sh[t];
    if (t == 1023) g_bsums[blockIdx.x] = sh[t];
}
__global__ void scan23_kernel(int n, int nb) {
    __shared__ int pre[64];
    if (threadIdx.x == 0) {
        int a = 0;
        for (int j = 0; j < nb; ++j) { pre[j] = a; a += g_bsums[j]; }
    }
    __syncthreads();
    int i = blockIdx.x * blockDim.x + threadIdx.x;
    if (i < n) {
        int incl = g_scan[i] + pre[i >> 10];
        g_roff[i + 1] = incl;
        g_fill[i] = incl - g_cnt[i];
        g_outr[i] = rsqrtf(fmaxf((float)g_outd[i], 1.0f));
        if (i == 0) g_roff[0] = 0;
    }
}

// ---------------- phase4: fill + e_w passthrough | convert_feat(hi half) ----
__global__ void phase4_kernel(const int* __restrict__ src,
                              const int* __restrict__ dst,
                              const float* __restrict__ e_w,
                              const float* __restrict__ feat,
                              float* __restrict__ out_tail,
                              int e, int qh, int q, int HB) {
    int b = blockIdx.x, t = threadIdx.x;
    if (b < HB) {
        int i = b * 256 + t;
        if (i < e) {
            float w = e_w[i];
            int s = src[i];
            int p = atomicAdd(&g_fill[dst[i]], 1);
            g_esrc[p] = s;
            g_esc[p] = w * g_outr[s];
            out_tail[i] = w;          // e_w passthrough output
        }
    } else {
        int i = qh + (b - HB) * 256 + t;
        if (i < q) convert_feat_one(feat, i);
    }
}

// ---------------- aggregation (fp16 gather, bf16 hi/lo out) ----------------
__global__ void __launch_bounds__(512)
aggregate_kernel(int n) {
    int row  = blockIdx.x * 16 + (threadIdx.x >> 5);
    int lane = threadIdx.x & 31;
    if (row >= n) return;
    int beg = g_roff[row], end = g_roff[row + 1];
    float a[8];
    #pragma unroll
    for (int j = 0; j < 8; ++j) a[j] = 0.f;
    for (int base = beg; base < end; base += 32) {
        int m = min(32, end - base);
        int sE = 0; float cE = 0.f;
        if (lane < m) { sE = g_esrc[base + lane]; cE = g_esc[base + lane]; }
        #pragma unroll 4
        for (int j = 0; j < m; ++j) {
            int   ss = __shfl_sync(0xffffffffu, sE, j);
            float sc = __shfl_sync(0xffffffffu, cE, j);
            uint4 d = *(const uint4*)(g_feat16 + (size_t)ss * F + lane * 8);
            float2 f0 = __half22float2(*(__half2*)&d.x);
            float2 f1 = __half22float2(*(__half2*)&d.y);
            float2 f2 = __half22float2(*(__half2*)&d.z);
            float2 f3 = __half22float2(*(__half2*)&d.w);
            a[0] += f0.x * sc; a[1] += f0.y * sc;
            a[2] += f1.x * sc; a[3] += f1.y * sc;
            a[4] += f2.x * sc; a[5] += f2.y * sc;
            a[6] += f3.x * sc; a[7] += f3.y * sc;
        }
    }
    float si = rsqrtf(fmaxf((float)(end - beg), 1.0f));
    __nv_bfloat16 h[8], l[8];
    #pragma unroll
    for (int j = 0; j < 8; ++j) cvt_hl(a[j] * si, h[j], l[j]);
    uint4 H = make_uint4(pk(h[0], h[1]), pk(h[2], h[3]), pk(h[4], h[5]), pk(h[6], h[7]));
    uint4 L = make_uint4(pk(l[0], l[1]), pk(l[2], l[3]), pk(l[4], l[5]), pk(l[6], l[7]));
    *(uint4*)(g_aggH + (size_t)row * F + lane * 8) = H;
    *(uint4*)(g_aggL + (size_t)row * F + lane * 8) = L;
    if (lane == 0) g_sin[row] = si;
}

// ---------------- bf16 3-term split GEMM (mma.sync, 3-stage pipeline) -------
#define A_STRIDE 40
#define B_STRIDE 136
#define ST_ELEMS 18944           // 128*40*2 + 32*136*2
#define AH_OFF(s) ((s) * ST_ELEMS)
#define AL_OFF(s) ((s) * ST_ELEMS + 5120)
#define BH_OFF(s) ((s) * ST_ELEMS + 10240)
#define BL_OFF(s) ((s) * ST_ELEMS + 14592)
#define NSTAGE 3
#define SMEM_DYN (NSTAGE * ST_ELEMS * 2)

__device__ __forceinline__ void load_stage(uint32_t sb, int stage, int it,
                                           int mBase, int nBase, int n, int tid) {
    int p = it >> 3, kc = it & 7, k0 = kc * 32;
    const __nv_bfloat16* AH = p ? g_aggH : g_featH;
    const __nv_bfloat16* AL = p ? g_aggL : g_featL;
    const __nv_bfloat16* BH = p ? g_wH : g_wsH;
    const __nv_bfloat16* BL = p ? g_wL : g_wsL;
    #pragma unroll
    for (int u = 0; u < 2; ++u) {
        int idx = u * 256 + tid;
        int row = idx >> 2, un = idx & 3;
        int gr = mBase + row;
        int grc = min(gr, n - 1);
        size_t go = (size_t)grc * F + k0 + un * 8;
        int sz = (gr < n) ? 16 : 0;
        uint32_t doff = (uint32_t)(row * A_STRIDE + un * 8) * 2;
        cp16z(sb + (uint32_t)AH_OFF(stage) * 2 + doff, AH + go, sz);
        cp16z(sb + (uint32_t)AL_OFF(stage) * 2 + doff, AL + go, sz);
    }
    #pragma unroll
    for (int u = 0; u < 2; ++u) {
        int idx = u * 256 + tid;
        int row = idx >> 4, un = idx & 15;
        size_t go = (size_t)(k0 + row) * F + nBase + un * 8;
        uint32_t doff = (uint32_t)(row * B_STRIDE + un * 8) * 2;
        cp16(sb + (uint32_t)BH_OFF(stage) * 2 + doff, BH + go);
        cp16(sb + (uint32_t)BL_OFF(stage) * 2 + doff, BL + go);
    }
}

__global__ void __launch_bounds__(256, 2)
gemm_kernel(const float* __restrict__ bias, float* __restrict__ out, int n) {
    extern __shared__ __align__(128) char smraw[];
    __nv_bfloat16* base = (__nv_bfloat16*)smraw;
    uint32_t sb = sptr(smraw);

    int tid = threadIdx.x;
    int wid = tid >> 5, lane = tid & 31;
    int wm = wid & 3, wn = wid >> 2;
    int mBase = (blockIdx.x >> 1) * 128;
    int nBase = (blockIdx.x & 1) * 128;

    float acc[2][8][4];
    #pragma unroll
    for (int i = 0; i < 2; ++i)
        #pragma unroll
        for (int j = 0; j < 8; ++j)
            #pragma unroll
            for (int q = 0; q < 4; ++q) acc[i][j][q] = 0.f;

    load_stage(sb, 0, 0, mBase, nBase, n, tid); cp_commit();
    load_stage(sb, 1, 1, mBase, nBase, n, tid); cp_commit();

    #pragma unroll 1
    for (int it = 0; it < 16; ++it) {
        if (it < 15) cp_wait1(); else cp_wait0();
        __syncthreads();
        int st = it % NSTAGE;
        #pragma unroll
        for (int kt = 0; kt < 2; ++kt) {
            int ks = kt * 16;
            unsigned aH[2][4], aL[2][4];
            #pragma unroll
            for (int mt = 0; mt < 2; ++mt) {
                int r = wm * 32 + mt * 16 + (lane & 15);
                int c = ks + (lane >> 4) * 8;
                ldsm4(aH[mt], sptr(base + AH_OFF(st) + r * A_STRIDE + c));
                ldsm4(aL[mt], sptr(base + AL_OFF(st) + r * A_STRIDE + c));
            }
            #pragma unroll
            for (int nc = 0; nc < 4; ++nc) {
                int rB = ks + (lane & 15);
                int cB = wn * 64 + nc * 16 + (lane >> 4) * 8;
                unsigned bH[4], bL[4];
                ldsm4t(bH, sptr(base + BH_OFF(st) + rB * B_STRIDE + cB));
                ldsm4t(bL, sptr(base + BL_OFF(st) + rB * B_STRIDE + cB));
                #pragma unroll
                for (int mt = 0; mt < 2; ++mt) {
                    mma_bf16(acc[mt][nc * 2],     aH[mt], bH[0], bH[1]);
                    mma_bf16(acc[mt][nc * 2],     aL[mt], bH[0], bH[1]);
                    mma_bf16(acc[mt][nc * 2],     aH[mt], bL[0], bL[1]);
                    mma_bf16(acc[mt][nc * 2 + 1], aH[mt], bH[2], bH[3]);
                    mma_bf16(acc[mt][nc * 2 + 1], aL[mt], bH[2], bH[3]);
                    mma_bf16(acc[mt][nc * 2 + 1], aH[mt], bL[2], bL[3]);
                }
            }
        }
        if (it + 2 < 16) {
            load_stage(sb, (it + 2) % NSTAGE, it + 2, mBase, nBase, n, tid);
            cp_commit();
        }
    }

    // epilogue: out = acc + s_in * bias
    #pragma unroll
    for (int mt = 0; mt < 2; ++mt) {
        int r0 = mBase + wm * 32 + mt * 16 + (lane >> 2);
        int r1 = r0 + 8;
        float si0 = (r0 < n) ? g_sin[r0] : 0.f;
        float si1 = (r1 < n) ? g_sin[r1] : 0.f;
        #pragma unroll
        for (int nt = 0; nt < 8; ++nt) {
            int c = nBase + wn * 64 + nt * 8 + (lane & 3) * 2;
            float b0 = bias[c], b1 = bias[c + 1];
            float* d = acc[mt][nt];
            if (r0 < n)
                *(float2*)(out + (size_t)r0 * F + c) =
                    make_float2(d[0] + si0 * b0, d[1] + si0 * b1);
            if (r1 < n)
                *(float2*)(out + (size_t)r1 * F + c) =
                    make_float2(d[2] + si1 * b0, d[3] + si1 * b1);
        }
    }
}

extern "C" void kernel_launch(void* const* d_in, const int* in_sizes, int n_in,
                              void* d_out, int out_size) {
    const float* feature = (const float*)d_in[0];
    const float* e_w     = (const float*)d_in[1];
    const float* W_self  = (const float*)d_in[4];
    const float* W       = (const float*)d_in[5];
    const float* b       = (const float*)d_in[6];
    const int*   src     = (const int*)d_in[7];
    const int*   dst     = (const int*)d_in[8];
    float*       out     = (float*)d_out;

    int n = in_sizes[0] / F;
    int e = in_sizes[1];
    int q  = n * (F / 4);          // float4 items of feature
    int qh = q / 2;

    static int smem_set = 0;
    if (!smem_set) {
        cudaFuncSetAttribute(gemm_kernel,
                             cudaFuncAttributeMaxDynamicSharedMemorySize, SMEM_DYN);
        smem_set = 1;
    }

    int HB = (e + 255) / 256;                 // hist/fill blocks
    int CB = (qh + 255) / 256;                // convert half blocks
    int WB = (F * F + 255) / 256;

    zero_kernel<<<(n + 255) / 256, 256>>>(n);
    phase2_kernel<<<HB + CB + WB, 256>>>(src, dst, feature, W_self, W, e, qh, HB, CB);
    int nb = (n + 1023) / 1024;
    scan1_kernel<<<nb, 1024>>>(n);
    scan23_kernel<<<(n + 255) / 256, 256>>>(n, nb);
    phase4_kernel<<<HB + ((q - qh + 255) / 256), 256>>>(src, dst, e_w, feature,
                                                        out + (size_t)n * F,
                                                        e, qh, q, HB);
    aggregate_kernel<<<(n + 15) / 16, 512>>>(n);

    int rb = (n + 127) / 128;
    gemm_kernel<<<rb * 2, 256, SMEM_DYN>>>(b, out, n);
}